// round 1
// baseline (speedup 1.0000x reference)
#include <cuda_runtime.h>

// CapsuleLayer dynamic routing, fully fused.
// C=10, B=128, N=1152, IN=8, OUT=16, 3 iterations.
//
// Insight: logits updates broadcast across the OUT axis, so logits are a
// scalar per (c,b,n). One CTA handles one (c, pair-of-b): computes the
// priors tile in smem, then runs all 3 routing iterations on-chip.

#define CCAP   10
#define BDIM   128
#define NDIM   1152
#define INDIM  8
#define OUTDIM 16
#define TBATCH 2
#define NBLOCKS (CCAP * BDIM / TBATCH)   // 640
#define THREADS 576                      // 18 warps; 1152 = 2*576 = 36*32
#define NGROUPS 36                       // THREADS/16
#define NWARPS  18
#define NPAD   1154                      // 1154 % 32 == 2 -> conflict-free [o][n] access

// shared memory layout (in floats)
#define PRI_SZ   (TBATCH * OUTDIM * NPAD)        // 36928
#define LG_OFF   PRI_SZ
#define LG_SZ    (TBATCH * NDIM)                 // 2304
#define WREDO_OFF (LG_OFF + LG_SZ)               // 18*16 = 288
#define WREDS_OFF (WREDO_OFF + NWARPS * OUTDIM)  // 18
#define RMAX_OFF  (WREDS_OFF + NWARPS)           // 18
#define OUTV_OFF  (RMAX_OFF + NWARPS)            // 32
#define SMEM_FLOATS (OUTV_OFF + TBATCH * OUTDIM)
#define SMEM_BYTES  (SMEM_FLOATS * 4)            // 158,352 B

__global__ __launch_bounds__(THREADS, 1)
void caps_routing_kernel(const float* __restrict__ x,
                         const float* __restrict__ W,
                         float* __restrict__ out)
{
    extern __shared__ float sm[];
    float* pri   = sm;                 // [TBATCH][OUTDIM][NPAD]
    float* lg    = sm + LG_OFF;        // [TBATCH][NDIM]
    float* wredo = sm + WREDO_OFF;     // [NWARPS][OUTDIM]
    float* wreds = sm + WREDS_OFF;     // [NWARPS]
    float* rmax  = sm + RMAX_OFF;      // [NWARPS]
    float* outv  = sm + OUTV_OFF;      // [TBATCH][OUTDIM]

    const int tid = threadIdx.x;
    const int c   = blockIdx.x >> 6;          // /64 pairs
    const int b0  = (blockIdx.x & 63) * 2;

    const float4* __restrict__ X4 = (const float4*)x;
    const float4* __restrict__ W4 = (const float4*)W;

    // ---------------- Phase A: priors GEMM into smem ----------------
    // thread t owns route nodes n = t and n = t + 576.
    #pragma unroll 1
    for (int rep = 0; rep < 2; rep++) {
        const int n = tid + rep * THREADS;

        float4 t0 = X4[((size_t)b0 * NDIM + n) * 2 + 0];
        float4 t1 = X4[((size_t)b0 * NDIM + n) * 2 + 1];
        float4 t2 = X4[((size_t)(b0 + 1) * NDIM + n) * 2 + 0];
        float4 t3 = X4[((size_t)(b0 + 1) * NDIM + n) * 2 + 1];
        float xa[8] = {t0.x, t0.y, t0.z, t0.w, t1.x, t1.y, t1.z, t1.w};
        float xb[8] = {t2.x, t2.y, t2.z, t2.w, t3.x, t3.y, t3.z, t3.w};

        float acc0[16], acc1[16];
        #pragma unroll
        for (int k = 0; k < 16; k++) { acc0[k] = 0.f; acc1[k] = 0.f; }

        const float4* wb = W4 + ((size_t)c * NDIM + n) * 32;  // 8*16 floats = 32 float4
        #pragma unroll
        for (int i = 0; i < 8; i++) {
            const float va = xa[i], vb = xb[i];
            #pragma unroll
            for (int k = 0; k < 4; k++) {
                float4 w = wb[i * 4 + k];
                acc0[4*k+0] += va * w.x; acc0[4*k+1] += va * w.y;
                acc0[4*k+2] += va * w.z; acc0[4*k+3] += va * w.w;
                acc1[4*k+0] += vb * w.x; acc1[4*k+1] += vb * w.y;
                acc1[4*k+2] += vb * w.z; acc1[4*k+3] += vb * w.w;
            }
        }
        // transposed store: pri[bb][o][n]; consecutive lanes -> consecutive n,
        // conflict-free.
        #pragma unroll
        for (int o = 0; o < 16; o++) {
            pri[o * NPAD + n]                    = acc0[o];
            pri[OUTDIM * NPAD + o * NPAD + n]    = acc1[o];
        }
    }
    // init logits
    for (int n = tid; n < TBATCH * NDIM; n += THREADS) lg[n] = 0.f;
    __syncthreads();

    // ---------------- Phase B: 3 routing iterations ----------------
    const int o    = tid & 15;
    const int g    = tid >> 4;      // 0..35  (n = g, g+36, ... : exactly 32 iters)
    const int warp = tid >> 5;      // 0..17
    const int lane = tid & 31;

    #pragma unroll 1
    for (int it = 0; it < 3; it++) {
        #pragma unroll 1
        for (int bb = 0; bb < TBATCH; bb++) {
            float* lgb  = lg + bb * NDIM;
            float* prib = pri + bb * OUTDIM * NPAD;

            // --- block max of logits (for stable softmax) ---
            float m = -1e30f;
            #pragma unroll
            for (int r = 0; r < 2; r++) m = fmaxf(m, lgb[tid + r * THREADS]);
            #pragma unroll
            for (int d = 16; d; d >>= 1)
                m = fmaxf(m, __shfl_xor_sync(0xffffffffu, m, d));
            if (lane == 0) rmax[warp] = m;
            __syncthreads();
            m = rmax[0];
            #pragma unroll
            for (int w = 1; w < NWARPS; w++) m = fmaxf(m, rmax[w]);

            // --- fused exp + weighted accumulation ---
            // lanes 0-15 of each warp share one n-stream, lanes 16-31 the next;
            // pri reads hit 32 distinct banks (NPAD % 32 == 2).
            float sp = 0.f, op = 0.f;
            #pragma unroll 4
            for (int n = g; n < NDIM; n += NGROUPS) {
                float e = __expf(lgb[n] - m);
                sp += e;
                op += e * prib[o * NPAD + n];
            }
            op += __shfl_xor_sync(0xffffffffu, op, 16);
            sp += __shfl_xor_sync(0xffffffffu, sp, 16);
            if (lane < 16) {
                wredo[warp * OUTDIM + o] = op;
                if (lane == 0) wreds[warp] = sp;
            }
            __syncthreads();

            // --- final 18-way reduce + squash (threads 0..15 = warp0 lanes) ---
            if (tid < 16) {
                float O = 0.f, S = 0.f;
                #pragma unroll
                for (int w = 0; w < NWARPS; w++) {
                    O += wredo[w * OUTDIM + tid];
                    S += wreds[w];
                }
                float t = O / S;                       // softmax-weighted sum
                float sq = t * t;
                #pragma unroll
                for (int d = 8; d; d >>= 1)
                    sq += __shfl_xor_sync(0x0000ffffu, sq, d, 16);
                float scale = sq / ((1.f + sq) * sqrtf(sq + 1e-8f));
                float val = t * scale;
                outv[bb * OUTDIM + tid] = val;
                if (it == 2)
                    out[((size_t)(c * BDIM + b0 + bb)) * OUTDIM + tid] = val;
            }
            __syncthreads();

            // --- logit update (skip on last iteration) ---
            if (it < 2) {
                const float ov = outv[bb * OUTDIM + o];
                #pragma unroll 4
                for (int n = g; n < NDIM; n += NGROUPS) {
                    float p = ov * prib[o * NPAD + n];
                    p += __shfl_xor_sync(0xffffffffu, p, 1);
                    p += __shfl_xor_sync(0xffffffffu, p, 2);
                    p += __shfl_xor_sync(0xffffffffu, p, 4);
                    p += __shfl_xor_sync(0xffffffffu, p, 8);
                    if (o == 0) lgb[n] += p;
                }
                __syncthreads();
            }
        }
    }
}

extern "C" void kernel_launch(void* const* d_in, const int* in_sizes, int n_in,
                              void* d_out, int out_size)
{
    const float* x = (const float*)d_in[0];
    const float* W = (const float*)d_in[1];
    // defensive: identify by size (x: 128*1152*8 = 1,179,648; W: 10*1152*8*16 = 1,474,560)
    if (n_in >= 2 && in_sizes[0] == CCAP * NDIM * INDIM * OUTDIM) {
        x = (const float*)d_in[1];
        W = (const float*)d_in[0];
    }
    float* out = (float*)d_out;

    cudaFuncSetAttribute(caps_routing_kernel,
                         cudaFuncAttributeMaxDynamicSharedMemorySize, SMEM_BYTES);
    caps_routing_kernel<<<NBLOCKS, THREADS, SMEM_BYTES>>>(x, W, out);
}

// round 3
// speedup vs baseline: 1.6263x; 1.6263x over previous
#include <cuda_runtime.h>

// CapsuleLayer dynamic routing, fully fused, register-resident routing.
// C=10, B=128, N=1152, IN=8, OUT=16, 3 iterations.
//
// One CTA per (c, batch-pair): 576 threads. Thread t owns route node n1=t
// (both batches, priors in registers) and node n2=t+576 (both batches,
// priors in smem). Logits are 4 thread-local registers. Routing iterations
// use warp shuffle reductions (batch-merging component-splitting butterfly).

#define CCAP   10
#define BD     128
#define ND     1152
#define OUTD   16
#define HALF   576
#define THREADS 576
#define NWARPS  18
#define NBLOCKS (CCAP * BD / 2)   // 640

// shared memory layout (floats)
#define PRI_SZ    (2 * 16 * HALF)          // 18432 : pri_s[bb][o][n1]
#define VRED_OFF  PRI_SZ
#define VRED_SZ   (NWARPS * 32)            // 576
#define SPRED_OFF (VRED_OFF + VRED_SZ)     // 36
#define WMAX_OFF  (SPRED_OFF + 2 * NWARPS) // 36
#define OUTV_OFF  (WMAX_OFF + 2 * NWARPS)  // 32
#define SMEM_FLOATS (OUTV_OFF + 32)
#define SMEM_BYTES  (SMEM_FLOATS * 4)      // ~76.3 KB

__global__ __launch_bounds__(THREADS, 1)
void caps_routing_kernel(const float* __restrict__ x,
                         const float* __restrict__ W,
                         float* __restrict__ out)
{
    extern __shared__ float sm[];
    float* pri_s = sm;                 // [2][16][HALF]
    float* vred  = sm + VRED_OFF;      // [18][32]
    float* spred = sm + SPRED_OFF;     // [18][2]
    float* wmax  = sm + WMAX_OFF;      // [18][2]
    float* outv  = sm + OUTV_OFF;      // [2][16]

    const int tid  = threadIdx.x;
    const int lane = tid & 31;
    const int w    = tid >> 5;           // 0..17
    const int c    = blockIdx.x >> 6;
    const int b0   = (blockIdx.x & 63) * 2;

    const float4* __restrict__ X4 = (const float4*)x;
    const float4* __restrict__ W4 = (const float4*)W;

    // ---------------- Phase A: priors ----------------
    // rows (n1, b0), (n1, b1) -> registers; (n2, b0), (n2, b1) -> smem.
    float priA0[16], priA1[16];
    float la0 = 0.f, la1 = 0.f, lb0 = 0.f, lb1 = 0.f;  // logits

    #pragma unroll
    for (int rep = 0; rep < 2; rep++) {
        const int n = tid + rep * HALF;
        float4 x00 = X4[((size_t)b0 * ND + n) * 2 + 0];
        float4 x01 = X4[((size_t)b0 * ND + n) * 2 + 1];
        float4 x10 = X4[((size_t)(b0 + 1) * ND + n) * 2 + 0];
        float4 x11 = X4[((size_t)(b0 + 1) * ND + n) * 2 + 1];
        float xa[8] = {x00.x, x00.y, x00.z, x00.w, x01.x, x01.y, x01.z, x01.w};
        float xb[8] = {x10.x, x10.y, x10.z, x10.w, x11.x, x11.y, x11.z, x11.w};

        float acc0[16], acc1[16];
        #pragma unroll
        for (int o = 0; o < 16; o++) { acc0[o] = 0.f; acc1[o] = 0.f; }

        const float4* wp = W4 + ((size_t)c * ND + n) * 32;  // 8*16 floats
        #pragma unroll
        for (int i = 0; i < 8; i++) {
            const float va = xa[i], vb = xb[i];
            #pragma unroll
            for (int q = 0; q < 4; q++) {
                float4 wv = wp[i * 4 + q];
                acc0[4*q+0] += va * wv.x; acc0[4*q+1] += va * wv.y;
                acc0[4*q+2] += va * wv.z; acc0[4*q+3] += va * wv.w;
                acc1[4*q+0] += vb * wv.x; acc1[4*q+1] += vb * wv.y;
                acc1[4*q+2] += vb * wv.z; acc1[4*q+3] += vb * wv.w;
            }
        }
        if (rep == 0) {
            #pragma unroll
            for (int o = 0; o < 16; o++) { priA0[o] = acc0[o]; priA1[o] = acc1[o]; }
        } else {
            #pragma unroll
            for (int o = 0; o < 16; o++) {
                pri_s[o * HALF + tid]              = acc0[o];   // bb=0
                pri_s[(16 + o) * HALF + tid]       = acc1[o];   // bb=1
            }
        }
    }
    __syncthreads();

    const float* __restrict__ prow0 = pri_s + tid;              // + o*HALF (bb=0)
    const float* __restrict__ prow1 = pri_s + 16 * HALF + tid;  // + o*HALF (bb=1)

    // ---------------- Phase B: 3 routing iterations ----------------
    #pragma unroll 1
    for (int it = 0; it < 3; it++) {
        // --- per-batch block max of logits ---
        float m0 = fmaxf(la0, lb0);
        float m1 = fmaxf(la1, lb1);
        #pragma unroll
        for (int d = 16; d; d >>= 1) {
            m0 = fmaxf(m0, __shfl_xor_sync(0xffffffffu, m0, d));
            m1 = fmaxf(m1, __shfl_xor_sync(0xffffffffu, m1, d));
        }
        if (lane == 0) { wmax[w * 2] = m0; wmax[w * 2 + 1] = m1; }
        __syncthreads();
        m0 = wmax[0]; m1 = wmax[1];
        #pragma unroll
        for (int j = 1; j < NWARPS; j++) {
            m0 = fmaxf(m0, wmax[j * 2]);
            m1 = fmaxf(m1, wmax[j * 2 + 1]);
        }

        // --- exp + weighted accumulation ---
        float ea0 = __expf(la0 - m0), ea1 = __expf(la1 - m1);
        float eb0 = __expf(lb0 - m0), eb1 = __expf(lb1 - m1);
        float sp0 = ea0 + eb0, sp1 = ea1 + eb1;

        float v0[16], v1[16];
        #pragma unroll
        for (int o = 0; o < 16; o++) {
            v0[o] = ea0 * priA0[o] + eb0 * prow0[o * HALF];
            v1[o] = ea1 * priA1[o] + eb1 * prow1[o * HALF];
        }

        // batch-merging reduce: after bit-16 step, lanes<16 carry batch0,
        // lanes>=16 carry batch1. Then split components over bits 8/4/2/1.
        float v[16];
        #pragma unroll
        for (int k = 0; k < 16; k++) {
            float s = (lane & 16) ? v0[k] : v1[k];     // send the one not kept
            float r = __shfl_xor_sync(0xffffffffu, s, 16);
            v[k] = ((lane & 16) ? v1[k] : v0[k]) + r;
        }
        #pragma unroll
        for (int k = 0; k < 8; k++) {
            float s = (lane & 8) ? v[k] : v[k + 8];
            float r = __shfl_xor_sync(0xffffffffu, s, 8);
            v[k] = ((lane & 8) ? v[k + 8] : v[k]) + r;
        }
        #pragma unroll
        for (int k = 0; k < 4; k++) {
            float s = (lane & 4) ? v[k] : v[k + 4];
            float r = __shfl_xor_sync(0xffffffffu, s, 4);
            v[k] = ((lane & 4) ? v[k + 4] : v[k]) + r;
        }
        #pragma unroll
        for (int k = 0; k < 2; k++) {
            float s = (lane & 2) ? v[k] : v[k + 2];
            float r = __shfl_xor_sync(0xffffffffu, s, 2);
            v[k] = ((lane & 2) ? v[k + 2] : v[k]) + r;
        }
        {
            float s = (lane & 1) ? v[0] : v[1];
            float r = __shfl_xor_sync(0xffffffffu, s, 1);
            v[0] = ((lane & 1) ? v[1] : v[0]) + r;
        }
        // v[0] = warp sum of component (lane&15), batch (lane>>4)

        {   // sp: same merge then butterfly
            float s = (lane & 16) ? sp0 : sp1;
            float r = __shfl_xor_sync(0xffffffffu, s, 16);
            float sp = ((lane & 16) ? sp1 : sp0) + r;
            #pragma unroll
            for (int d = 8; d; d >>= 1)
                sp += __shfl_xor_sync(0xffffffffu, sp, d);
            if ((lane & 15) == 0) spred[w * 2 + (lane >> 4)] = sp;
        }
        vred[w * 32 + lane] = v[0];
        __syncthreads();

        // --- final 18-way reduce + squash (warp 0: lanes 0-15 bb0, 16-31 bb1) ---
        if (tid < 32) {
            const int fb = tid >> 4;
            float O = 0.f, S = 0.f;
            #pragma unroll
            for (int j = 0; j < NWARPS; j++) {
                O += vred[j * 32 + tid];
                S += spred[j * 2 + fb];
            }
            float t = O / S;
            float sq = t * t;
            #pragma unroll
            for (int d = 8; d; d >>= 1)
                sq += __shfl_xor_sync(0xffffffffu, sq, d);
            float scale = sq / ((1.f + sq) * sqrtf(sq + 1e-8f));
            float val = t * scale;
            outv[tid] = val;
            if (it == 2)
                out[((size_t)(c * BD + b0 + fb)) * OUTD + (tid & 15)] = val;
        }
        __syncthreads();

        // --- logit update: register dot products ---
        if (it < 2) {
            float da0 = 0.f, da1 = 0.f, db0 = 0.f, db1 = 0.f;
            #pragma unroll
            for (int o = 0; o < 16; o++) {
                const float o0 = outv[o];        // LDS broadcast
                const float o1 = outv[16 + o];
                da0 += o0 * priA0[o];
                da1 += o1 * priA1[o];
                db0 += o0 * prow0[o * HALF];
                db1 += o1 * prow1[o * HALF];
            }
            la0 += da0; la1 += da1; lb0 += db0; lb1 += db1;
        }
    }
}

extern "C" void kernel_launch(void* const* d_in, const int* in_sizes, int n_in,
                              void* d_out, int out_size)
{
    const float* x = (const float*)d_in[0];
    const float* W = (const float*)d_in[1];
    // defensive: identify by size (x: 1,179,648 ; W: 1,474,560)
    if (n_in >= 2 && in_sizes[0] == CCAP * ND * 8 * OUTD) {
        x = (const float*)d_in[1];
        W = (const float*)d_in[0];
    }
    float* out = (float*)d_out;

    cudaFuncSetAttribute(caps_routing_kernel,
                         cudaFuncAttributeMaxDynamicSharedMemorySize, SMEM_BYTES);
    caps_routing_kernel<<<NBLOCKS, THREADS, SMEM_BYTES>>>(x, W, out);
}